// round 1
// baseline (speedup 1.0000x reference)
#include <cuda_runtime.h>

#define NK 256   // clusters
#define ND 64    // dims

// Precomputed ||c_k||^2
__device__ float g_csq[NK];

__global__ void csq_kernel(const float* __restrict__ c) {
    int k = threadIdx.x;
    if (k < NK) {
        const float4* c4 = reinterpret_cast<const float4*>(c) + k * (ND / 4);
        float s0 = 0.f, s1 = 0.f, s2 = 0.f, s3 = 0.f;
#pragma unroll
        for (int j = 0; j < ND / 4; ++j) {
            float4 v = c4[j];
            s0 = fmaf(v.x, v.x, s0);
            s1 = fmaf(v.y, v.y, s1);
            s2 = fmaf(v.z, v.z, s2);
            s3 = fmaf(v.w, v.w, s3);
        }
        g_csq[k] = (s0 + s1) + (s2 + s3);
    }
}

// One thread per point. x row in registers; centroids via L1 (64KB, warp-uniform
// broadcast reads). Distance via the reference's expansion form:
//   d = (||x||^2 - 2*(x.c)) + ||c||^2
// with the 2*t multiply kept un-fused (__fmul_rn) to mimic the reference's
// separate-multiply rounding, and 4-way split accumulators for the dot
// (close to blocked/tree accumulation -> smaller deviation from XLA's matmul).
__global__ __launch_bounds__(256) void assign_kernel(
    const float* __restrict__ x,
    const float* __restrict__ c,
    float* __restrict__ out_assign,
    int n)
{
    int i = blockIdx.x * 256 + threadIdx.x;
    if (i >= n) return;

    const float4* xrow = reinterpret_cast<const float4*>(x) + (size_t)i * (ND / 4);
    float4 xr[ND / 4];
#pragma unroll
    for (int j = 0; j < ND / 4; ++j) xr[j] = xrow[j];

    // ||x||^2 (4-way split)
    float xs0 = 0.f, xs1 = 0.f, xs2 = 0.f, xs3 = 0.f;
#pragma unroll
    for (int j = 0; j < ND / 4; ++j) {
        xs0 = fmaf(xr[j].x, xr[j].x, xs0);
        xs1 = fmaf(xr[j].y, xr[j].y, xs1);
        xs2 = fmaf(xr[j].z, xr[j].z, xs2);
        xs3 = fmaf(xr[j].w, xr[j].w, xs3);
    }
    float xsq = (xs0 + xs1) + (xs2 + xs3);

    const float4* c4 = reinterpret_cast<const float4*>(c);

    float best = 3.402823466e38f;
    int bestk = 0;

#pragma unroll 4
    for (int k = 0; k < NK; ++k) {
        const float4* crow = c4 + k * (ND / 4);
        float t0 = 0.f, t1 = 0.f, t2 = 0.f, t3 = 0.f;
#pragma unroll
        for (int j = 0; j < ND / 4; ++j) {
            float4 cv = __ldg(crow + j);
            t0 = fmaf(xr[j].x, cv.x, t0);
            t1 = fmaf(xr[j].y, cv.y, t1);
            t2 = fmaf(xr[j].z, cv.z, t2);
            t3 = fmaf(xr[j].w, cv.w, t3);
        }
        float t = (t0 + t1) + (t2 + t3);
        // un-fused 2*t to match reference rounding: (xsq - 2*t) + csq
        float dist = (xsq - __fmul_rn(2.0f, t)) + g_csq[k];
        if (dist < best) { best = dist; bestk = k; }  // strict '<' = first-occurrence argmin
    }

    out_assign[i] = (float)bestk;
}

extern "C" void kernel_launch(void* const* d_in, const int* in_sizes, int n_in,
                              void* d_out, int out_size) {
    const float* x = (const float*)d_in[0];        // [N, 64]
    const float* c = (const float*)d_in[1];        // [256, 64]
    float* out = (float*)d_out;                    // [256*64 centroids | N assignments]

    int n = in_sizes[0] / ND;

    // Output part 1: centroids passthrough (reference returns centroids[None,:,:])
    cudaMemcpyAsync(out, c, (size_t)NK * ND * sizeof(float),
                    cudaMemcpyDeviceToDevice, 0);

    // ||c||^2 once
    csq_kernel<<<1, NK>>>(c);

    // Output part 2: assignments (as float, after the 16384 centroid floats)
    int grid = (n + 255) / 256;
    assign_kernel<<<grid, 256>>>(x, c, out + NK * ND, n);
}

// round 2
// speedup vs baseline: 1.4418x; 1.4418x over previous
#include <cuda_runtime.h>
#include <cstdint>

#define NK 256   // clusters
#define ND 64    // dims

// Precomputed ||c_k||^2
__device__ float g_csq[NK];

__global__ void csq_kernel(const float* __restrict__ c) {
    int k = threadIdx.x;
    if (k < NK) {
        const float4* c4 = reinterpret_cast<const float4*>(c) + k * (ND / 4);
        float s0 = 0.f, s1 = 0.f, s2 = 0.f, s3 = 0.f;
#pragma unroll
        for (int j = 0; j < ND / 4; ++j) {
            float4 v = c4[j];
            s0 = fmaf(v.x, v.x, s0);
            s1 = fmaf(v.y, v.y, s1);
            s2 = fmaf(v.z, v.z, s2);
            s3 = fmaf(v.w, v.w, s3);
        }
        g_csq[k] = (s0 + s1) + (s2 + s3);
    }
}

// ---- packed fp32x2 helpers (sm_100a native; PTX-only) ----
__device__ __forceinline__ uint64_t fma2(uint64_t a, uint64_t b, uint64_t c) {
    uint64_t d;
    asm("fma.rn.f32x2 %0, %1, %2, %3;" : "=l"(d) : "l"(a), "l"(b), "l"(c));
    return d;
}
__device__ __forceinline__ uint64_t add2(uint64_t a, uint64_t b) {
    uint64_t d;
    asm("add.rn.f32x2 %0, %1, %2;" : "=l"(d) : "l"(a), "l"(b));
    return d;
}
__device__ __forceinline__ float2 unpack2(uint64_t a) {
    float2 f;
    asm("mov.b64 {%0, %1}, %2;" : "=f"(f.x), "=f"(f.y) : "l"(a));
    return f;
}

// P=2 points per thread, both x rows resident in registers as packed f32x2
// pairs (adjacent d-dims share a 64-bit reg — the natural memory layout, so
// packing is free). Centroid tile re-read per k as 16 uniform LDG.128
// (L1-resident, broadcast) now feeds 128 FMAs instead of 64.
// Accumulation: 2 packed chains per point = 4-way scalar split, identical
// shape to round 1 (which matched the reference argmin bitwise).
__global__ __launch_bounds__(256) void assign_kernel(
    const float* __restrict__ x,
    const float* __restrict__ c,
    float* __restrict__ out_assign,
    int n)
{
    int t = blockIdx.x * 256 + threadIdx.x;
    int p0 = t * 2;
    if (p0 >= n) return;
    int p1 = p0 + 1;
    int p1c = (p1 < n) ? p1 : p0;   // clamp loads; store guarded below

    // Load both x rows: 32 floats -> 16 ulonglong2 each -> 32 packed f32x2 regs
    const ulonglong2* xr0p = reinterpret_cast<const ulonglong2*>(x) + (size_t)p0 * (ND / 4);
    const ulonglong2* xr1p = reinterpret_cast<const ulonglong2*>(x) + (size_t)p1c * (ND / 4);
    uint64_t xr0[ND / 2], xr1[ND / 2];
#pragma unroll
    for (int j = 0; j < ND / 4; ++j) {
        ulonglong2 v0 = xr0p[j];
        ulonglong2 v1 = xr1p[j];
        xr0[2 * j] = v0.x; xr0[2 * j + 1] = v0.y;
        xr1[2 * j] = v1.x; xr1[2 * j + 1] = v1.y;
    }

    // ||x||^2 per point (packed, 2-chain = 4-way scalar split)
    uint64_t q0 = 0ull, q1 = 0ull, r0 = 0ull, r1 = 0ull;
#pragma unroll
    for (int j = 0; j < ND / 4; ++j) {
        q0 = fma2(xr0[2 * j],     xr0[2 * j],     q0);
        q1 = fma2(xr0[2 * j + 1], xr0[2 * j + 1], q1);
        r0 = fma2(xr1[2 * j],     xr1[2 * j],     r0);
        r1 = fma2(xr1[2 * j + 1], xr1[2 * j + 1], r1);
    }
    float2 qf = unpack2(add2(q0, q1));
    float2 rf = unpack2(add2(r0, r1));
    float xsq0 = qf.x + qf.y;
    float xsq1 = rf.x + rf.y;

    const ulonglong2* c2 = reinterpret_cast<const ulonglong2*>(c);

    float best0 = 3.402823466e38f, best1 = 3.402823466e38f;
    int bk0 = 0, bk1 = 0;

#pragma unroll 2
    for (int k = 0; k < NK; ++k) {
        const ulonglong2* crow = c2 + k * (ND / 4);
        uint64_t a0 = 0ull, a1 = 0ull, b0 = 0ull, b1 = 0ull;
#pragma unroll
        for (int j = 0; j < ND / 4; ++j) {
            ulonglong2 cc = __ldg(crow + j);
            a0 = fma2(xr0[2 * j],     cc.x, a0);
            a1 = fma2(xr0[2 * j + 1], cc.y, a1);
            b0 = fma2(xr1[2 * j],     cc.x, b0);
            b1 = fma2(xr1[2 * j + 1], cc.y, b1);
        }
        float2 sa = unpack2(add2(a0, a1));
        float2 sb = unpack2(add2(b0, b1));
        float t0 = sa.x + sa.y;
        float t1 = sb.x + sb.y;
        float csq = g_csq[k];
        // fmaf(-2,t,xsq) == (xsq - 2*t) unfused, since *2 is exact
        float d0 = fmaf(-2.0f, t0, xsq0) + csq;
        float d1 = fmaf(-2.0f, t1, xsq1) + csq;
        if (d0 < best0) { best0 = d0; bk0 = k; }
        if (d1 < best1) { best1 = d1; bk1 = k; }
    }

    out_assign[p0] = (float)bk0;
    if (p1 < n) out_assign[p1] = (float)bk1;
}

extern "C" void kernel_launch(void* const* d_in, const int* in_sizes, int n_in,
                              void* d_out, int out_size) {
    const float* x = (const float*)d_in[0];        // [N, 64]
    const float* c = (const float*)d_in[1];        // [256, 64]
    float* out = (float*)d_out;                    // [256*64 centroids | N assignments]

    int n = in_sizes[0] / ND;

    cudaMemcpyAsync(out, c, (size_t)NK * ND * sizeof(float),
                    cudaMemcpyDeviceToDevice, 0);

    csq_kernel<<<1, NK>>>(c);

    int pts_per_block = 256 * 2;
    int grid = (n + pts_per_block - 1) / pts_per_block;
    assign_kernel<<<grid, 256>>>(x, c, out + NK * ND, n);
}

// round 4
// speedup vs baseline: 1.9733x; 1.3687x over previous
#include <cuda_runtime.h>
#include <cstdint>

#define NK 256   // clusters
#define ND 64    // dims

// Precomputed ||c_k||^2
__device__ float g_csq[NK];

__global__ void csq_kernel(const float* __restrict__ c) {
    int k = threadIdx.x;
    if (k < NK) {
        const float4* c4 = reinterpret_cast<const float4*>(c) + k * (ND / 4);
        float s0 = 0.f, s1 = 0.f, s2 = 0.f, s3 = 0.f;
#pragma unroll
        for (int j = 0; j < ND / 4; ++j) {
            float4 v = c4[j];
            s0 = fmaf(v.x, v.x, s0);
            s1 = fmaf(v.y, v.y, s1);
            s2 = fmaf(v.z, v.z, s2);
            s3 = fmaf(v.w, v.w, s3);
        }
        g_csq[k] = (s0 + s1) + (s2 + s3);
    }
}

// ---- packed fp32x2 helpers (sm_100a native; PTX-only) ----
__device__ __forceinline__ uint64_t fma2(uint64_t a, uint64_t b, uint64_t c) {
    uint64_t d;
    asm("fma.rn.f32x2 %0, %1, %2, %3;" : "=l"(d) : "l"(a), "l"(b), "l"(c));
    return d;
}
__device__ __forceinline__ float2 unpack2(uint64_t a) {
    float2 f;
    asm("mov.b64 {%0, %1}, %2;" : "=f"(f.x), "=f"(f.y) : "l"(a));
    return f;
}

// packed (1.0f, 1.0f): multiplying by it is exact, so fma2(a1, ONE2, a0)
// is bit-identical to add.rn.f32x2(a0, a1).
#define ONE2 0x3F8000003F800000ull

// Load half a centroid row (32 floats) into 16 packed-u64 regs via 8 LDG.128.
__device__ __forceinline__ void load_half(uint64_t* B, const ulonglong2* p) {
#pragma unroll
    for (int j = 0; j < 8; ++j) {
        ulonglong2 v = __ldg(p + j);
        B[2 * j] = v.x;
        B[2 * j + 1] = v.y;
    }
}

// P=2 points/thread, x rows register-resident as packed f32x2 (128 regs).
// Centroid rows streamed through a half-row (32-float) register ping-pong:
// loads for the next half-row are issued BEFORE the FMAs of the current
// half, giving every load ~32 FMA-issue slots (>=40 cyc) of slack to cover
// L1-hit latency. Per-k arithmetic identical to rounds 1/2 (4-way split
// chains, fmaf(-2,t,xsq)+csq, strict-< argmin) -> rel_err stays 0.
__global__ __launch_bounds__(128, 2) void assign_kernel(
    const float* __restrict__ x,
    const float* __restrict__ c,
    float* __restrict__ out_assign,
    int n)
{
    int t = blockIdx.x * 128 + threadIdx.x;
    int p0 = t * 2;
    if (p0 >= n) return;
    int p1 = p0 + 1;
    int p1c = (p1 < n) ? p1 : p0;

    // x rows: 32 packed-u64 regs each
    const ulonglong2* xr0p = reinterpret_cast<const ulonglong2*>(x) + (size_t)p0 * (ND / 4);
    const ulonglong2* xr1p = reinterpret_cast<const ulonglong2*>(x) + (size_t)p1c * (ND / 4);
    uint64_t xr0[ND / 2], xr1[ND / 2];
#pragma unroll
    for (int j = 0; j < ND / 4; ++j) {
        ulonglong2 v0 = xr0p[j];
        ulonglong2 v1 = xr1p[j];
        xr0[2 * j] = v0.x; xr0[2 * j + 1] = v0.y;
        xr1[2 * j] = v1.x; xr1[2 * j + 1] = v1.y;
    }

    // ||x||^2 (same split shape as before)
    uint64_t q0 = 0ull, q1 = 0ull, r0 = 0ull, r1 = 0ull;
#pragma unroll
    for (int j = 0; j < ND / 4; ++j) {
        q0 = fma2(xr0[2 * j],     xr0[2 * j],     q0);
        q1 = fma2(xr0[2 * j + 1], xr0[2 * j + 1], q1);
        r0 = fma2(xr1[2 * j],     xr1[2 * j],     r0);
        r1 = fma2(xr1[2 * j + 1], xr1[2 * j + 1], r1);
    }
    float2 qf = unpack2(fma2(q1, ONE2, q0));
    float2 rf = unpack2(fma2(r1, ONE2, r0));
    float xsq0 = qf.x + qf.y;
    float xsq1 = rf.x + rf.y;

    const ulonglong2* c2 = reinterpret_cast<const ulonglong2*>(c);

    float best0 = 3.402823466e38f, best1 = 3.402823466e38f;
    int bk0 = 0, bk1 = 0;

    // half-row ping-pong buffers (16 u64 regs each)
    uint64_t BA[16], BB[16];

    // prologue: first half of row 0
    load_half(BA, c2);

#pragma unroll 1
    for (int k = 0; k < NK; ++k) {
        const ulonglong2* row = c2 + k * (ND / 4);

        // in-flight: second half of row k
        load_half(BB, row + 8);

        uint64_t a0 = 0ull, a1 = 0ull, b0 = 0ull, b1 = 0ull;
        // FMA first half (x u64 indices 0..15) from BA
#pragma unroll
        for (int j = 0; j < 8; ++j) {
            a0 = fma2(xr0[2 * j],     BA[2 * j],     a0);
            a1 = fma2(xr0[2 * j + 1], BA[2 * j + 1], a1);
            b0 = fma2(xr1[2 * j],     BA[2 * j],     b0);
            b1 = fma2(xr1[2 * j + 1], BA[2 * j + 1], b1);
        }

        // in-flight: first half of row k+1 (wrap-safe reload of row 0 at end)
        int kn = (k + 1) & (NK - 1);
        load_half(BA, c2 + kn * (ND / 4));

        // FMA second half (x u64 indices 16..31) from BB
#pragma unroll
        for (int j = 0; j < 8; ++j) {
            a0 = fma2(xr0[16 + 2 * j], BB[2 * j],     a0);
            a1 = fma2(xr0[17 + 2 * j], BB[2 * j + 1], a1);
            b0 = fma2(xr1[16 + 2 * j], BB[2 * j],     b0);
            b1 = fma2(xr1[17 + 2 * j], BB[2 * j + 1], b1);
        }

        // epilogue — identical rounding to rounds 1/2
        float2 fa = unpack2(fma2(a1, ONE2, a0));
        float2 fb = unpack2(fma2(b1, ONE2, b0));
        float t0 = fa.x + fa.y;
        float t1 = fb.x + fb.y;
        float csq = g_csq[k];
        float d0 = fmaf(-2.0f, t0, xsq0) + csq;
        float d1 = fmaf(-2.0f, t1, xsq1) + csq;
        if (d0 < best0) { best0 = d0; bk0 = k; }
        if (d1 < best1) { best1 = d1; bk1 = k; }
    }

    out_assign[p0] = (float)bk0;
    if (p1 < n) out_assign[p1] = (float)bk1;
}

extern "C" void kernel_launch(void* const* d_in, const int* in_sizes, int n_in,
                              void* d_out, int out_size) {
    const float* x = (const float*)d_in[0];        // [N, 64]
    const float* c = (const float*)d_in[1];        // [256, 64]
    float* out = (float*)d_out;                    // [256*64 centroids | N assignments]

    int n = in_sizes[0] / ND;

    cudaMemcpyAsync(out, c, (size_t)NK * ND * sizeof(float),
                    cudaMemcpyDeviceToDevice, 0);

    csq_kernel<<<1, NK>>>(c);

    int pts_per_block = 128 * 2;
    int grid = (n + pts_per_block - 1) / pts_per_block;
    assign_kernel<<<grid, 128>>>(x, c, out + NK * ND, n);
}